// round 1
// baseline (speedup 1.0000x reference)
#include <cuda_runtime.h>

// ---------------------------------------------------------------------------
// MNIST TWN CNN forward, batch 4096, fp32.
// Pipeline:
//   quantize weights (ternary, exact vs reference)
//   conv1(1->32,5x5) -> BN(train) -> ReLU -> maxpool2   [recompute: stats pass + apply pass]
//   conv2(32->64,5x5) -> BN -> ReLU -> maxpool2         [store y2, then bn+pool pass]
//   fc1(1024->512) -> BN -> ReLU                        [GEMM + column stats, then fused into fc2]
//   fc2(512->10) + bf2                                  -> out [4096,10]
// All conv/fc biases except bf2 cancel exactly under training-mode BN.
// ---------------------------------------------------------------------------

#define NIMG 4096

// ---- device scratch (static allocations only; no cudaMalloc anywhere) ----
static __device__ float g_w1q[32 * 25];
static __device__ float g_w2q[64 * 32 * 25];
static __device__ float g_wf1q[512 * 1024];
static __device__ float g_wf2q[10 * 512];

static __device__ unsigned int g_absmax[4];

static __device__ double g_sum1[32],  g_sqs1[32];
static __device__ double g_sum2[64],  g_sqs2[64];
static __device__ double g_sum3[512], g_sqs3[512];

static __device__ float g_sc1[32],  g_sh1[32];
static __device__ float g_sc2[64],  g_sh2[64];
static __device__ float g_sc3[512], g_sh3[512];

static __device__ float g_h1[NIMG * 32 * 144];   // pooled conv1 out [n][c][12][12]  (75.5 MB)
static __device__ float g_y2[NIMG * 64 * 64];    // conv2 raw out    [n][c][8][8]    (67 MB)
static __device__ float g_h2[NIMG * 1024];       // pooled conv2 out, flattened      (16.8 MB)
static __device__ float g_y3[NIMG * 512];        // fc1 raw out                      (8.4 MB)

// ---------------------------------------------------------------------------
__global__ void k_zero() {
    int t = threadIdx.x;
    if (t < 4)  g_absmax[t] = 0u;
    if (t < 32) { g_sum1[t] = 0.0; g_sqs1[t] = 0.0; }
    if (t < 64) { g_sum2[t] = 0.0; g_sqs2[t] = 0.0; }
    g_sum3[t] = 0.0; g_sqs3[t] = 0.0;   // blockDim.x == 512
}

// ---- abs-max per weight tensor (monotone uint compare on |w| bits) --------
__global__ void k_absmax(const float* __restrict__ w1, const float* __restrict__ w2,
                         const float* __restrict__ wf1, const float* __restrict__ wf2) {
    int tid = blockIdx.x * blockDim.x + threadIdx.x;
    int stride = gridDim.x * blockDim.x;
    float m0 = 0.f, m1 = 0.f, m2 = 0.f, m3 = 0.f;
    for (int i = tid; i < 800;    i += stride) m0 = fmaxf(m0, fabsf(w1[i]));
    for (int i = tid; i < 51200;  i += stride) m1 = fmaxf(m1, fabsf(w2[i]));
    for (int i = tid; i < 524288; i += stride) m2 = fmaxf(m2, fabsf(wf1[i]));
    for (int i = tid; i < 5120;   i += stride) m3 = fmaxf(m3, fabsf(wf2[i]));
    #pragma unroll
    for (int off = 16; off; off >>= 1) {
        m0 = fmaxf(m0, __shfl_xor_sync(0xffffffffu, m0, off));
        m1 = fmaxf(m1, __shfl_xor_sync(0xffffffffu, m1, off));
        m2 = fmaxf(m2, __shfl_xor_sync(0xffffffffu, m2, off));
        m3 = fmaxf(m3, __shfl_xor_sync(0xffffffffu, m3, off));
    }
    if ((threadIdx.x & 31) == 0) {
        atomicMax(&g_absmax[0], __float_as_uint(m0));
        atomicMax(&g_absmax[1], __float_as_uint(m1));
        atomicMax(&g_absmax[2], __float_as_uint(m2));
        atomicMax(&g_absmax[3], __float_as_uint(m3));
    }
}

__device__ __forceinline__ float ternary(float w, float t) {
    return (w > t ? 1.0f : 0.0f) - (w < -t ? 1.0f : 0.0f);
}

__global__ void k_quant(const float* __restrict__ w1, const float* __restrict__ w2,
                        const float* __restrict__ wf1, const float* __restrict__ wf2) {
    float t0 = 0.05f * __uint_as_float(g_absmax[0]);
    float t1 = 0.05f * __uint_as_float(g_absmax[1]);
    float t2 = 0.05f * __uint_as_float(g_absmax[2]);
    float t3 = 0.05f * __uint_as_float(g_absmax[3]);
    int tid = blockIdx.x * blockDim.x + threadIdx.x;
    int stride = gridDim.x * blockDim.x;
    for (int i = tid; i < 800;    i += stride) g_w1q[i]  = ternary(w1[i],  t0);
    for (int i = tid; i < 51200;  i += stride) g_w2q[i]  = ternary(w2[i],  t1);
    for (int i = tid; i < 524288; i += stride) g_wf1q[i] = ternary(wf1[i], t2);
    for (int i = tid; i < 5120;   i += stride) g_wf2q[i] = ternary(wf2[i], t3);
}

// ---------------------------------------------------------------------------
// conv1 stats: per-channel sum / sumsq of raw conv output (bias cancels in BN).
// Thread computes 8 (n,oy,ox) positions x 32 channels; warp->shared->global(double).
// ---------------------------------------------------------------------------
__global__ __launch_bounds__(256) void k_conv1_stats(const float* __restrict__ x) {
    __shared__ float ws[800];
    __shared__ float ssum[32], ssq[32];
    for (int i = threadIdx.x; i < 800; i += 256) ws[i] = g_w1q[i];
    if (threadIdx.x < 32) { ssum[threadIdx.x] = 0.f; ssq[threadIdx.x] = 0.f; }
    __syncthreads();

    float acc[32], acc2[32];
    #pragma unroll
    for (int c = 0; c < 32; c++) { acc[c] = 0.f; acc2[c] = 0.f; }

    int base = blockIdx.x * 2048 + threadIdx.x;
    for (int it = 0; it < 8; it++) {
        int pos = base + it * 256;                 // < 4096*576 = 2359296
        int n  = pos / 576;
        int r  = pos - n * 576;
        int oy = r / 24;
        int ox = r - oy * 24;
        const float* xp = x + n * 784 + oy * 28 + ox;
        float p[25];
        #pragma unroll
        for (int ky = 0; ky < 5; ky++)
            #pragma unroll
            for (int kx = 0; kx < 5; kx++) p[ky * 5 + kx] = xp[ky * 28 + kx];
        #pragma unroll
        for (int c = 0; c < 32; c++) {
            float v = 0.f;
            #pragma unroll
            for (int k = 0; k < 25; k++) v = fmaf(p[k], ws[c * 25 + k], v);
            acc[c] += v;
            acc2[c] = fmaf(v, v, acc2[c]);
        }
    }
    int lane = threadIdx.x & 31;
    #pragma unroll
    for (int c = 0; c < 32; c++) {
        float s = acc[c], q = acc2[c];
        #pragma unroll
        for (int off = 16; off; off >>= 1) {
            s += __shfl_xor_sync(0xffffffffu, s, off);
            q += __shfl_xor_sync(0xffffffffu, q, off);
        }
        if (lane == 0) { atomicAdd(&ssum[c], s); atomicAdd(&ssq[c], q); }
    }
    __syncthreads();
    if (threadIdx.x < 32) {
        atomicAdd(&g_sum1[threadIdx.x], (double)ssum[threadIdx.x]);
        atomicAdd(&g_sqs1[threadIdx.x], (double)ssq[threadIdx.x]);
    }
}

__global__ void k_fin1(const float* __restrict__ g, const float* __restrict__ be) {
    int i = threadIdx.x;
    if (i >= 32) return;
    const double invM = 1.0 / (4096.0 * 576.0);
    double mean = g_sum1[i] * invM;
    double var  = g_sqs1[i] * invM - mean * mean;
    float A = g[i] * rsqrtf((float)var + 1e-5f);
    g_sc1[i] = A;
    g_sh1[i] = be[i] - (float)mean * A;
}

// ---------------------------------------------------------------------------
// conv1 apply: recompute conv for the 2x2 pool window, BN affine, relu(max).
// Thread = (n, pooled y, pooled x), all 32 channels. Writes g_h1 [n][c][12][12].
// ---------------------------------------------------------------------------
__global__ __launch_bounds__(256) void k_conv1_apply(const float* __restrict__ x) {
    __shared__ float ws[800];
    __shared__ float sA[32], sB[32];
    for (int i = threadIdx.x; i < 800; i += 256) ws[i] = g_w1q[i];
    if (threadIdx.x < 32) { sA[threadIdx.x] = g_sc1[threadIdx.x]; sB[threadIdx.x] = g_sh1[threadIdx.x]; }
    __syncthreads();

    int idx = blockIdx.x * 256 + threadIdx.x;      // < 4096*144 = 589824
    int n = idx / 144;
    int r = idx - n * 144;
    int py = r / 12;
    int px = r - py * 12;
    const float* xp = x + n * 784 + py * 2 * 28 + px * 2;
    float p[36];
    #pragma unroll
    for (int iy = 0; iy < 6; iy++)
        #pragma unroll
        for (int ix = 0; ix < 6; ix++) p[iy * 6 + ix] = xp[iy * 28 + ix];

    float* hp = g_h1 + n * 4608 + r;
    for (int c = 0; c < 32; c++) {
        float v0 = 0.f, v1 = 0.f, v2 = 0.f, v3 = 0.f;
        #pragma unroll
        for (int ky = 0; ky < 5; ky++)
            #pragma unroll
            for (int kx = 0; kx < 5; kx++) {
                float w = ws[c * 25 + ky * 5 + kx];
                v0 = fmaf(p[ky * 6 + kx],           w, v0);
                v1 = fmaf(p[ky * 6 + kx + 1],       w, v1);
                v2 = fmaf(p[(ky + 1) * 6 + kx],     w, v2);
                v3 = fmaf(p[(ky + 1) * 6 + kx + 1], w, v3);
            }
        float A = sA[c], B = sB[c];
        float m = fmaxf(fmaxf(fmaf(A, v0, B), fmaf(A, v1, B)),
                        fmaxf(fmaf(A, v2, B), fmaf(A, v3, B)));
        hp[c * 144] = fmaxf(m, 0.f);
    }
}

// ---------------------------------------------------------------------------
// conv2: one CTA per image (h1 slice in SMEM). Thread = (cout, out-row),
// computes 8 output px. Stores y2 and accumulates per-channel stats.
// ---------------------------------------------------------------------------
__global__ __launch_bounds__(512) void k_conv2() {
    __shared__ float sin_[32 * 144];               // 18 KB
    int tid = threadIdx.x;
    int n = blockIdx.x;
    const float* src = g_h1 + n * 4608;
    for (int i = tid; i < 4608; i += 512) sin_[i] = src[i];
    __syncthreads();

    int c  = tid >> 3;                             // 0..63
    int py = tid & 7;                              // 0..7
    const float* wp = g_w2q + c * 800;

    float acc[8];
    #pragma unroll
    for (int px = 0; px < 8; px++) acc[px] = 0.f;

    for (int ci = 0; ci < 32; ci++) {
        const float* base = sin_ + ci * 144;
        #pragma unroll
        for (int ky = 0; ky < 5; ky++) {
            const float4* row = (const float4*)(base + (py + ky) * 12);
            float4 qa = row[0], qb = row[1], qc = row[2];
            float rr[12] = { qa.x, qa.y, qa.z, qa.w, qb.x, qb.y, qb.z, qb.w,
                             qc.x, qc.y, qc.z, qc.w };
            const float* wr = wp + ci * 25 + ky * 5;
            float w[5] = { wr[0], wr[1], wr[2], wr[3], wr[4] };
            #pragma unroll
            for (int kx = 0; kx < 5; kx++)
                #pragma unroll
                for (int px = 0; px < 8; px++)
                    acc[px] = fmaf(rr[px + kx], w[kx], acc[px]);
        }
    }

    float s = 0.f, q = 0.f;
    float* dst = g_y2 + n * 4096 + c * 64 + py * 8;
    #pragma unroll
    for (int px = 0; px < 8; px++) {
        float v = acc[px];
        dst[px] = v;
        s += v;
        q = fmaf(v, v, q);
    }
    // reduce over the 8 lanes sharing one channel
    #pragma unroll
    for (int off = 1; off < 8; off <<= 1) {
        s += __shfl_xor_sync(0xffffffffu, s, off);
        q += __shfl_xor_sync(0xffffffffu, q, off);
    }
    if (py == 0) {
        atomicAdd(&g_sum2[c], (double)s);
        atomicAdd(&g_sqs2[c], (double)q);
    }
}

__global__ void k_fin2(const float* __restrict__ g, const float* __restrict__ be) {
    int i = threadIdx.x;
    if (i >= 64) return;
    const double invM = 1.0 / (4096.0 * 64.0);
    double mean = g_sum2[i] * invM;
    double var  = g_sqs2[i] * invM - mean * mean;
    float A = g[i] * rsqrtf((float)var + 1e-5f);
    g_sc2[i] = A;
    g_sh2[i] = be[i] - (float)mean * A;
}

// bn + relu + 2x2 maxpool of y2 -> g_h2 (already in flatten order c*16+py*4+px)
__global__ __launch_bounds__(256) void k_bnpool2() {
    int idx = blockIdx.x * 256 + threadIdx.x;      // < 4096*1024
    int n = idx >> 10;
    int r = idx & 1023;
    int c = r >> 4;
    int pr = r & 15;
    int py = pr >> 2, px = pr & 3;
    const float* src = g_y2 + n * 4096 + c * 64 + py * 2 * 8 + px * 2;
    float A = g_sc2[c], B = g_sh2[c];
    float m = fmaxf(fmaxf(fmaf(A, src[0], B), fmaf(A, src[1], B)),
                    fmaxf(fmaf(A, src[8], B), fmaf(A, src[9], B)));
    g_h2[idx] = fmaxf(m, 0.f);
}

// ---------------------------------------------------------------------------
// fc1 GEMM: y3[4096,512] = h2[4096,1024] @ wf1q[512,1024]^T  (+ column stats)
// 64x64 tile, BK=16, 256 threads, 4x4 register tile.
// ---------------------------------------------------------------------------
__global__ __launch_bounds__(256) void k_fc1() {
    __shared__ float As[16][64];
    __shared__ float Bs[16][64];
    __shared__ float scol[64], scol2[64];
    int tid = threadIdx.x;
    if (tid < 64) { scol[tid] = 0.f; scol2[tid] = 0.f; }

    int m0 = blockIdx.y * 64;
    int n0 = blockIdx.x * 64;
    int lr = tid >> 2;             // 0..63
    int lk = (tid & 3) * 4;        // 0,4,8,12
    const float* Aload = g_h2  + (m0 + lr) * 1024 + lk;
    const float* Bload = g_wf1q + (n0 + lr) * 1024 + lk;
    int tx = tid & 15, ty = tid >> 4;

    float acc[4][4];
    #pragma unroll
    for (int i = 0; i < 4; i++)
        #pragma unroll
        for (int j = 0; j < 4; j++) acc[i][j] = 0.f;

    for (int k0 = 0; k0 < 1024; k0 += 16) {
        float4 av = *(const float4*)(Aload + k0);
        float4 bv = *(const float4*)(Bload + k0);
        __syncthreads();
        As[lk + 0][lr] = av.x; As[lk + 1][lr] = av.y; As[lk + 2][lr] = av.z; As[lk + 3][lr] = av.w;
        Bs[lk + 0][lr] = bv.x; Bs[lk + 1][lr] = bv.y; Bs[lk + 2][lr] = bv.z; Bs[lk + 3][lr] = bv.w;
        __syncthreads();
        #pragma unroll
        for (int k = 0; k < 16; k++) {
            float4 a = *(const float4*)&As[k][ty * 4];
            float4 b = *(const float4*)&Bs[k][tx * 4];
            acc[0][0] = fmaf(a.x, b.x, acc[0][0]); acc[0][1] = fmaf(a.x, b.y, acc[0][1]);
            acc[0][2] = fmaf(a.x, b.z, acc[0][2]); acc[0][3] = fmaf(a.x, b.w, acc[0][3]);
            acc[1][0] = fmaf(a.y, b.x, acc[1][0]); acc[1][1] = fmaf(a.y, b.y, acc[1][1]);
            acc[1][2] = fmaf(a.y, b.z, acc[1][2]); acc[1][3] = fmaf(a.y, b.w, acc[1][3]);
            acc[2][0] = fmaf(a.z, b.x, acc[2][0]); acc[2][1] = fmaf(a.z, b.y, acc[2][1]);
            acc[2][2] = fmaf(a.z, b.z, acc[2][2]); acc[2][3] = fmaf(a.z, b.w, acc[2][3]);
            acc[3][0] = fmaf(a.w, b.x, acc[3][0]); acc[3][1] = fmaf(a.w, b.y, acc[3][1]);
            acc[3][2] = fmaf(a.w, b.z, acc[3][2]); acc[3][3] = fmaf(a.w, b.w, acc[3][3]);
        }
    }
    #pragma unroll
    for (int i = 0; i < 4; i++) {
        int row = m0 + ty * 4 + i;
        float4 o = make_float4(acc[i][0], acc[i][1], acc[i][2], acc[i][3]);
        *(float4*)(g_y3 + row * 512 + n0 + tx * 4) = o;
    }
    #pragma unroll
    for (int j = 0; j < 4; j++) {
        float s = 0.f, q = 0.f;
        #pragma unroll
        for (int i = 0; i < 4; i++) { s += acc[i][j]; q = fmaf(acc[i][j], acc[i][j], q); }
        atomicAdd(&scol[tx * 4 + j], s);
        atomicAdd(&scol2[tx * 4 + j], q);
    }
    __syncthreads();
    if (tid < 64) {
        atomicAdd(&g_sum3[n0 + tid], (double)scol[tid]);
        atomicAdd(&g_sqs3[n0 + tid], (double)scol2[tid]);
    }
}

__global__ void k_fin3(const float* __restrict__ g, const float* __restrict__ be) {
    int i = threadIdx.x;
    if (i >= 512) return;
    const double invM = 1.0 / 4096.0;
    double mean = g_sum3[i] * invM;
    double var  = g_sqs3[i] * invM - mean * mean;
    float A = g[i] * rsqrtf((float)var + 1e-5f);
    g_sc3[i] = A;
    g_sh3[i] = be[i] - (float)mean * A;
}

// ---------------------------------------------------------------------------
// fc2 fused with bn1d+relu: warp per row, weights staged in SMEM.
// ---------------------------------------------------------------------------
__global__ __launch_bounds__(256) void k_fc2(float* __restrict__ out, const float* __restrict__ bf2) {
    __shared__ float sw[5120];
    __shared__ float sA[512], sB[512];
    __shared__ float sb[16];
    for (int i = threadIdx.x; i < 5120; i += 256) sw[i] = g_wf2q[i];
    for (int i = threadIdx.x; i < 512; i += 256) { sA[i] = g_sc3[i]; sB[i] = g_sh3[i]; }
    if (threadIdx.x < 10) sb[threadIdx.x] = bf2[threadIdx.x];
    __syncthreads();

    int warp = threadIdx.x >> 5, lane = threadIdx.x & 31;
    int n = blockIdx.x * 8 + warp;
    const float* yr = g_y3 + n * 512;
    float acc[10];
    #pragma unroll
    for (int o = 0; o < 10; o++) acc[o] = 0.f;
    for (int f = lane; f < 512; f += 32) {
        float a = fmaxf(fmaf(sA[f], yr[f], sB[f]), 0.f);
        #pragma unroll
        for (int o = 0; o < 10; o++) acc[o] = fmaf(a, sw[o * 512 + f], acc[o]);
    }
    #pragma unroll
    for (int o = 0; o < 10; o++) {
        float s = acc[o];
        #pragma unroll
        for (int off = 16; off; off >>= 1) s += __shfl_xor_sync(0xffffffffu, s, off);
        if (lane == 0) out[n * 10 + o] = s + sb[o];
    }
}

// ---------------------------------------------------------------------------
extern "C" void kernel_launch(void* const* d_in, const int* in_sizes, int n_in,
                              void* d_out, int out_size) {
    const float* x   = (const float*)d_in[0];
    const float* w1  = (const float*)d_in[1];
    const float* g1  = (const float*)d_in[3];
    const float* be1 = (const float*)d_in[4];
    const float* w2  = (const float*)d_in[5];
    const float* g2  = (const float*)d_in[7];
    const float* be2 = (const float*)d_in[8];
    const float* wf1 = (const float*)d_in[9];
    const float* g3  = (const float*)d_in[11];
    const float* be3 = (const float*)d_in[12];
    const float* wf2 = (const float*)d_in[13];
    const float* bf2 = (const float*)d_in[14];
    float* out = (float*)d_out;

    k_zero<<<1, 512>>>();
    k_absmax<<<96, 256>>>(w1, w2, wf1, wf2);
    k_quant<<<512, 256>>>(w1, w2, wf1, wf2);

    k_conv1_stats<<<1152, 256>>>(x);          // 2359296 positions / (256*8)
    k_fin1<<<1, 32>>>(g1, be1);
    k_conv1_apply<<<2304, 256>>>(x);          // 589824 pooled positions

    k_conv2<<<4096, 512>>>();
    k_fin2<<<1, 64>>>(g2, be2);
    k_bnpool2<<<16384, 256>>>();              // 4194304 pooled outputs

    dim3 g_fc1(8, 64);
    k_fc1<<<g_fc1, 256>>>();
    k_fin3<<<1, 512>>>(g3, be3);
    k_fc2<<<512, 256>>>(out, bf2);
}